// round 4
// baseline (speedup 1.0000x reference)
#include <cuda_runtime.h>
#include <cstdint>

// ---------------------------------------------------------------------------
// Multi-scale triplane encoder: scatter-mean of point features into 3 planes
// per scale. B=8, C=32, scales: (res=64, N=65536), (128, 32768), (256, 16384).
//
// Scatter with red.global.add.v4.f32 into channel-contiguous scratch
// (plane,b,cell,C); tiled smem transpose (+count divide) writes (B,C,res,res).
//
// Scratch invariant: g_scr/g_cnt are ALL-ZERO between kernel_launch calls.
// (__device__ globals are zero-initialized; the transpose restores zeros to
// every touched cell after reading it.) This removes the 264MB zero pass, and
// count==0 cells can skip the scratch read entirely (they are provably zero).
// ---------------------------------------------------------------------------

#define BATCH 8
#define CDIM 32

// scratch accumulator, same element count as output: 66,060,288 floats (264MB)
#define SCR_TOTAL 66060288
__device__ float g_scr[SCR_TOTAL];

// per-(scale,plane,batch,cell) counts: 2,064,384 floats
#define CNT_TOTAL 2064384
__device__ float g_cnt[CNT_TOTAL];

// scale bases (floats) — same for scratch and output
#define OFF0 0
#define OFF1 (3 * 8 * 32 * 64 * 64)                 //  3,145,728
#define OFF2 (OFF1 + 3 * 8 * 32 * 128 * 128)        // 15,728,640
#define CNT0 0
#define CNT1 (3 * 8 * 64 * 64)                      //  98,304
#define CNT2 (CNT1 + 3 * 8 * 128 * 128)             // 491,520

// ---------------------------------------------------------------------------
// Index math must match XLA bit-for-bit: x/C -> x*(1/C) (f32 folded), no FMA.
// ---------------------------------------------------------------------------

__device__ __forceinline__ int grid_idx(float v, float res) {
    const float R = (float)(1.0 / (double)1.10001f);
    float u = __fadd_rn(__fmul_rn(v, R), 0.5f);       // no fma contraction
    u = fminf(fmaxf(u, 0.0f), 0.99999f);
    return (int)(__fmul_rn(u, res));
}

__device__ __forceinline__ void red_v4(float* p, float a, float b, float c, float d) {
    asm volatile("red.global.add.v4.f32 [%0], {%1, %2, %3, %4};"
                 :: "l"(p), "f"(a), "f"(b), "f"(c), "f"(d)
                 : "memory");
}

template <int RES, int LOGN>
__device__ __forceinline__ void scatter_body(const float* __restrict__ f,
                                             const float* __restrict__ cd,
                                             int scr_off, int cnt_off, int gid) {
    const int R2 = RES * RES;
    int b = gid >> LOGN;

    float x = cd[gid * 3 + 0];
    float y = cd[gid * 3 + 1];
    float z = cd[gid * 3 + 2];
    int gx = grid_idx(x, (float)RES);
    int gy = grid_idx(y, (float)RES);
    int gz = grid_idx(z, (float)RES);

    int idx[3];
    idx[0] = gx + RES * gz;   // xz
    idx[1] = gx + RES * gy;   // xy
    idx[2] = gy + RES * gz;   // yz

    float4 feat[CDIM / 4];
    const float4* fv = reinterpret_cast<const float4*>(f + (size_t)gid * CDIM);
#pragma unroll
    for (int i = 0; i < CDIM / 4; i++) feat[i] = fv[i];

#pragma unroll
    for (int p = 0; p < 3; p++) {
        atomicAdd(&g_cnt[cnt_off + ((size_t)p * BATCH + b) * R2 + idx[p]], 1.0f);
        float* o = g_scr + scr_off +
                   (((size_t)p * BATCH + b) * R2 + idx[p]) * CDIM;  // 128B line
#pragma unroll
        for (int i = 0; i < CDIM / 4; i++) {
            red_v4(o + 4 * i, feat[i].x, feat[i].y, feat[i].z, feat[i].w);
        }
    }
}

// one merged launch for all three scales: blocks [0,2048) scale0,
// [2048,3072) scale1, [3072,3584) scale2.  256 threads/block.
__global__ void scatter_all_kernel(const float* __restrict__ f0, const float* __restrict__ c0,
                                   const float* __restrict__ f1, const float* __restrict__ c1,
                                   const float* __restrict__ f2, const float* __restrict__ c2) {
    int blk = blockIdx.x;
    int t = threadIdx.x;
    if (blk < 2048) {
        scatter_body<64, 16>(f0, c0, OFF0, CNT0, blk * 256 + t);
    } else if (blk < 3072) {
        scatter_body<128, 15>(f1, c1, OFF1, CNT1, (blk - 2048) * 256 + t);
    } else {
        scatter_body<256, 14>(f2, c2, OFF2, CNT2, (blk - 3072) * 256 + t);
    }
}

// ---------------------------------------------------------------------------
// Transpose (plane,b,cell,C) -> (plane,b,C,cell) with count divide.
// Block (32,8): 32x32 tile of (cell, channel). Per-cell predicate on count:
//   count==0  -> cell line is zero (invariant), skip read, emit zeros
//   count>0   -> read line, write zeros back (restore invariant)
// Counts for this tile are zeroed after the reads.
// ---------------------------------------------------------------------------

template <int RES>
__global__ void transpose_div_kernel(float* __restrict__ out,   // scale base
                                     int scr_off, int cnt_off) {
    const int R2 = RES * RES;
    __shared__ float tile[32][33];
    __shared__ float cdiv[32];
    int tx = threadIdx.x, ty = threadIdx.y;
    int cell0 = blockIdx.x * 32;
    int b = blockIdx.y;
    int p = blockIdx.z;

    size_t base = ((size_t)p * BATCH + b) * R2;
    float* cnt = g_cnt + cnt_off + base + cell0;
    float* src = g_scr + scr_off + (base + cell0) * CDIM;

#pragma unroll
    for (int k = 0; k < 4; k++) {
        int row = ty + 8 * k;                   // local cell
        float c = cnt[row];                     // uniform per warp
        if (c != 0.0f) {
            size_t off = (size_t)row * CDIM + tx;
            tile[row][tx] = src[off];
            src[off] = 0.0f;                    // restore scratch invariant
        } else {
            tile[row][tx] = 0.0f;
        }
        if (tx == 0) cdiv[row] = fmaxf(c, 1.0f);
    }
    __syncthreads();

    if (ty == 0) cnt[tx] = 0.0f;                // restore count invariant

    float* dst = out + (base * CDIM) + cell0;   // (p,b,C,R2) base + cell0
#pragma unroll
    for (int k = 0; k < 4; k++) {
        int c = ty + 8 * k;                     // channel
        dst[(size_t)c * R2 + tx] = __fdiv_rn(tile[tx][c], cdiv[tx]);
    }
}

// ---------------------------------------------------------------------------

extern "C" void kernel_launch(void* const* d_in, const int* in_sizes, int n_in,
                              void* d_out, int out_size) {
    // Match inputs by element count (all six are distinct).
    const float *f0 = nullptr, *f1 = nullptr, *f2 = nullptr;
    const float *c0 = nullptr, *c1 = nullptr, *c2 = nullptr;
    for (int i = 0; i < n_in; i++) {
        int s = in_sizes[i];
        const float* p = (const float*)d_in[i];
        if (s == 8 * 65536 * 32) f0 = p;
        else if (s == 8 * 32768 * 32) f1 = p;
        else if (s == 8 * 16384 * 32) f2 = p;
        else if (s == 8 * 65536 * 3) c0 = p;
        else if (s == 8 * 32768 * 3) c1 = p;
        else if (s == 8 * 16384 * 3) c2 = p;
    }

    float* out = (float*)d_out;

    // ---- scatter all scales (scratch is all-zero on entry by invariant) ----
    scatter_all_kernel<<<3584, 256>>>(f0, c0, f1, c1, f2, c2);

    // ---- transpose + divide into d_out; restores scratch/count zeros ----
    {
        dim3 g(64 * 64 / 32, BATCH, 3), blk(32, 8);
        transpose_div_kernel<64><<<g, blk>>>(out + OFF0, OFF0, CNT0);
    }
    {
        dim3 g(128 * 128 / 32, BATCH, 3), blk(32, 8);
        transpose_div_kernel<128><<<g, blk>>>(out + OFF1, OFF1, CNT1);
    }
    {
        dim3 g(256 * 256 / 32, BATCH, 3), blk(32, 8);
        transpose_div_kernel<256><<<g, blk>>>(out + OFF2, OFF2, CNT2);
    }
}

// round 5
// speedup vs baseline: 2.8981x; 2.8981x over previous
#include <cuda_runtime.h>
#include <cstdint>

// ---------------------------------------------------------------------------
// Multi-scale triplane encoder: scatter-mean of point features into 3 planes
// per scale. B=8, C=32, scales: (res=64, N=65536), (128, 32768), (256, 16384).
//
// Scatter with red.global.add.v4.f32 into channel-contiguous scratch
// (plane,b,cell,C); tiled smem transpose (+count divide) writes (B,C,res,res).
//
// Scratch invariant: g_scr/g_cnt are ALL-ZERO between kernel_launch calls.
// The transpose restores zeros to every touched cell after reading it, and
// count==0 cells skip the scratch read entirely (they are provably zero).
// ---------------------------------------------------------------------------

#define BATCH 8
#define CDIM 32

#define SCR_TOTAL 66060288          // 264MB scratch (same count as output)
__device__ float g_scr[SCR_TOTAL];
#define CNT_TOTAL 2064384
__device__ float g_cnt[CNT_TOTAL];

// scale bases (floats) — same for scratch and output
#define OFF0 0
#define OFF1 (3 * 8 * 32 * 64 * 64)                 //  3,145,728
#define OFF2 (OFF1 + 3 * 8 * 32 * 128 * 128)        // 15,728,640
#define CNT0 0
#define CNT1 (3 * 8 * 64 * 64)                      //  98,304
#define CNT2 (CNT1 + 3 * 8 * 128 * 128)             // 491,520

// ---------------------------------------------------------------------------
// Index math must match XLA bit-for-bit: x/C -> x*(1/C) (f32 folded), no FMA.
// ---------------------------------------------------------------------------

__device__ __forceinline__ int grid_idx(float v, float res) {
    const float R = (float)(1.0 / (double)1.10001f);
    float u = __fadd_rn(__fmul_rn(v, R), 0.5f);       // no fma contraction
    u = fminf(fmaxf(u, 0.0f), 0.99999f);
    return (int)(__fmul_rn(u, res));
}

__device__ __forceinline__ void red_v4(float* p, float a, float b, float c, float d) {
    asm volatile("red.global.add.v4.f32 [%0], {%1, %2, %3, %4};"
                 :: "l"(p), "f"(a), "f"(b), "f"(c), "f"(d)
                 : "memory");
}

template <int RES, int LOGN>
__device__ __forceinline__ void scatter_body(const float* __restrict__ f,
                                             const float* __restrict__ cd,
                                             int scr_off, int cnt_off, int gid) {
    const int R2 = RES * RES;
    int b = gid >> LOGN;

    float x = cd[gid * 3 + 0];
    float y = cd[gid * 3 + 1];
    float z = cd[gid * 3 + 2];
    int gx = grid_idx(x, (float)RES);
    int gy = grid_idx(y, (float)RES);
    int gz = grid_idx(z, (float)RES);

    int idx[3];
    idx[0] = gx + RES * gz;   // xz
    idx[1] = gx + RES * gy;   // xy
    idx[2] = gy + RES * gz;   // yz

    float4 feat[CDIM / 4];
    const float4* fv = reinterpret_cast<const float4*>(f + (size_t)gid * CDIM);
#pragma unroll
    for (int i = 0; i < CDIM / 4; i++) feat[i] = fv[i];

#pragma unroll
    for (int p = 0; p < 3; p++) {
        atomicAdd(&g_cnt[cnt_off + ((size_t)p * BATCH + b) * R2 + idx[p]], 1.0f);
        float* o = g_scr + scr_off +
                   (((size_t)p * BATCH + b) * R2 + idx[p]) * CDIM;  // 128B line
#pragma unroll
        for (int i = 0; i < CDIM / 4; i++) {
            red_v4(o + 4 * i, feat[i].x, feat[i].y, feat[i].z, feat[i].w);
        }
    }
}

// merged scatter: blocks [0,2048) scale0, [2048,3072) scale1, [3072,3584) scale2
__global__ void scatter_all_kernel(const float* __restrict__ f0, const float* __restrict__ c0,
                                   const float* __restrict__ f1, const float* __restrict__ c1,
                                   const float* __restrict__ f2, const float* __restrict__ c2) {
    int blk = blockIdx.x;
    int t = threadIdx.x;
    if (blk < 2048) {
        scatter_body<64, 16>(f0, c0, OFF0, CNT0, blk * 256 + t);
    } else if (blk < 3072) {
        scatter_body<128, 15>(f1, c1, OFF1, CNT1, (blk - 2048) * 256 + t);
    } else {
        scatter_body<256, 14>(f2, c2, OFF2, CNT2, (blk - 3072) * 256 + t);
    }
}

// ---------------------------------------------------------------------------
// Transpose (plane,b,cell,C) -> (plane,b,C,cell) with count divide.
// Block (32,8): 32x32 tile of (cell, channel). ALL count loads first, then
// ALL predicated src loads back-to-back (MLP=4), then stores — no per-
// iteration load->branch->load serial chain.
// Divide is one __frcp_rn per cell + per-element multiply (~1e-7 rel, OK).
// ---------------------------------------------------------------------------

template <int RES>
__device__ __forceinline__ void transpose_body(float* __restrict__ out,
                                               int scr_off, int cnt_off,
                                               int tile_x, int b, int p) {
    const int R2 = RES * RES;
    __shared__ float tile[32][33];
    __shared__ float crec[32];
    int tx = threadIdx.x, ty = threadIdx.y;
    int cell0 = tile_x * 32;

    size_t base = ((size_t)p * BATCH + b) * R2;
    float* cnt = g_cnt + cnt_off + base + cell0;
    float* src = g_scr + scr_off + (base + cell0) * CDIM;

    // 1) all count loads (L2-resident, warp-broadcast)
    float c[4];
#pragma unroll
    for (int k = 0; k < 4; k++) c[k] = cnt[ty + 8 * k];

    // 2) all src loads, predicated but issued together
    float v[4];
#pragma unroll
    for (int k = 0; k < 4; k++) {
        int row = ty + 8 * k;
        v[k] = (c[k] != 0.0f) ? src[(size_t)row * CDIM + tx] : 0.0f;
    }

    // 3) stores: smem tile, scratch zero-restore, reciprocal
#pragma unroll
    for (int k = 0; k < 4; k++) {
        int row = ty + 8 * k;
        tile[row][tx] = v[k];
        if (c[k] != 0.0f) src[(size_t)row * CDIM + tx] = 0.0f;
        if (tx == 0) crec[row] = __frcp_rn(fmaxf(c[k], 1.0f));
    }
    __syncthreads();

    if (ty == 0) cnt[tx] = 0.0f;                // restore count invariant

    float* dst = out + base * CDIM + cell0;     // (p,b,C,R2) base + cell0
    float r = crec[tx];
#pragma unroll
    for (int k = 0; k < 4; k++) {
        int ch = ty + 8 * k;
        dst[(size_t)ch * R2 + tx] = __fmul_rn(tile[tx][ch], r);
    }
}

// merged transpose: flat grid.x decodes (scale, tile, b, p)
// scale0: 128 tiles * 24 (b,p) = 3072 blocks
// scale1: 512 * 24 = 12288
// scale2: 2048 * 24 = 49152          total 64512
#define TR0 3072
#define TR1 (TR0 + 12288)
#define TR_TOTAL (TR1 + 49152)

__global__ void transpose_all_kernel(float* __restrict__ out) {
    int blk = blockIdx.x;
    if (blk < TR0) {
        int tile = blk & 127, bp = blk >> 7;          // 128 tiles
        transpose_body<64>(out + OFF0, OFF0, CNT0, tile, bp & 7, bp >> 3);
    } else if (blk < TR1) {
        int q = blk - TR0;
        int tile = q & 511, bp = q >> 9;              // 512 tiles
        transpose_body<128>(out + OFF1, OFF1, CNT1, tile, bp & 7, bp >> 3);
    } else {
        int q = blk - TR1;
        int tile = q & 2047, bp = q >> 11;            // 2048 tiles
        transpose_body<256>(out + OFF2, OFF2, CNT2, tile, bp & 7, bp >> 3);
    }
}

// ---------------------------------------------------------------------------

extern "C" void kernel_launch(void* const* d_in, const int* in_sizes, int n_in,
                              void* d_out, int out_size) {
    // Match inputs by element count (all six are distinct).
    const float *f0 = nullptr, *f1 = nullptr, *f2 = nullptr;
    const float *c0 = nullptr, *c1 = nullptr, *c2 = nullptr;
    for (int i = 0; i < n_in; i++) {
        int s = in_sizes[i];
        const float* p = (const float*)d_in[i];
        if (s == 8 * 65536 * 32) f0 = p;
        else if (s == 8 * 32768 * 32) f1 = p;
        else if (s == 8 * 16384 * 32) f2 = p;
        else if (s == 8 * 65536 * 3) c0 = p;
        else if (s == 8 * 32768 * 3) c1 = p;
        else if (s == 8 * 16384 * 3) c2 = p;
    }

    float* out = (float*)d_out;

    // scatter all scales (scratch all-zero on entry by invariant)
    scatter_all_kernel<<<3584, 256>>>(f0, c0, f1, c1, f2, c2);

    // transpose + divide into d_out; restores scratch/count zeros
    transpose_all_kernel<<<TR_TOTAL, dim3(32, 8)>>>(out);
}